// round 15
// baseline (speedup 1.0000x reference)
#include <cuda_runtime.h>
#include <cuda_bf16.h>

#define NN 50000
#define EE 800000
#define CC 128
#define HH 2
#define ETOT (EE + NN)   // edges + self loops
#define NBLK 196         // ceil(NN/256)
#define SMAX 160         // max degree buffer (graph max deg ~50)

// packed f32x2 helpers (Blackwell; ptxas never auto-emits FFMA2)
#define FFMA2(d, a, b) asm("fma.rn.f32x2 %0, %1, %2, %0;" : "+l"(d) : "l"(a), "l"(b))
#define PACK2(d, lo, hi) asm("mov.b64 %0, {%1, %2};" : "=l"(d) \
    : "r"(__float_as_uint(lo)), "r"(__float_as_uint(hi)))
#define UNPACK2(lo, hi, d) do { unsigned int _ul, _uh; \
    asm("mov.b64 {%0, %1}, %2;" : "=r"(_ul), "=r"(_uh) : "l"(d)); \
    lo = __uint_as_float(_ul); hi = __uint_as_float(_uh); } while (0)

// ---------------- scratch (device globals; no allocation allowed) -----------
__device__ float  g_xp[(size_t)NN * HH * CC];   // [N][H][C] projected features
__device__ float  g_ai[NN * HH];                // layer-1 src attention scalars
__device__ float  g_aj[NN * HH];                // layer-1 dst attention scalars
__device__ float  g_ai2[NN * HH];               // layer-2 src attention scalars
__device__ float  g_aj2[NN * HH];               // layer-2 dst attention scalars
__device__ float  g_x1[(size_t)NN * CC];        // layer-1 post-activation
__device__ float  g_pre[(size_t)NN * CC];       // layer-2 pre-activation (score)
__device__ int    g_cnt[NN];
__device__ int    g_rowptr[NN + 1];
__device__ int    g_cursor[NN];
__device__ int    g_src[ETOT];                  // CSR-by-dst: src node per slot
__device__ int    g_bsum[NBLK];
__device__ int    g_boff[NBLK];

// ---------------- init: cnt=1, zero all attn scalars ------------------------
__global__ void init_kernel() {
    int i = blockIdx.x * 256 + threadIdx.x;
    if (i < NN) g_cnt[i] = 1;   // self loop
    if (i < NN * HH) {
        g_ai[i] = 0.f;  g_aj[i] = 0.f;
        g_ai2[i] = 0.f; g_aj2[i] = 0.f;
    }
}

__global__ void count_kernel(const int* __restrict__ ei) {
    int e = blockIdx.x * 256 + threadIdx.x;
    if (e < EE) atomicAdd(&g_cnt[ei[EE + e]], 1);
}

// ---------------- 3-phase scan ----------------------------------------------
__global__ void scan_pass1() {
    __shared__ int sh[256];
    int idx = blockIdx.x * 256 + threadIdx.x;
    sh[threadIdx.x] = (idx < NN) ? g_cnt[idx] : 0;
    __syncthreads();
    for (int s = 128; s > 0; s >>= 1) {
        if (threadIdx.x < s) sh[threadIdx.x] += sh[threadIdx.x + s];
        __syncthreads();
    }
    if (threadIdx.x == 0) g_bsum[blockIdx.x] = sh[0];
}

__global__ void scan_pass2() {
    __shared__ int sh[256];
    int t = threadIdx.x;
    int v = (t < NBLK) ? g_bsum[t] : 0;
    sh[t] = v;
    __syncthreads();
    for (int off = 1; off < 256; off <<= 1) {
        int add = (t >= off) ? sh[t - off] : 0;
        __syncthreads();
        sh[t] += add;
        __syncthreads();
    }
    if (t < NBLK) g_boff[t] = sh[t] - v;   // exclusive
}

__global__ void scan_pass3() {
    __shared__ int sh[256];
    int b = blockIdx.x, t = threadIdx.x;
    int idx = b * 256 + t;
    int v = (idx < NN) ? g_cnt[idx] : 0;
    sh[t] = v;
    __syncthreads();
    for (int off = 1; off < 256; off <<= 1) {
        int add = (t >= off) ? sh[t - off] : 0;
        __syncthreads();
        sh[t] += add;
        __syncthreads();
    }
    int incl = sh[t];
    int base = g_boff[b];
    if (idx < NN) {
        int excl = base + incl - v;
        g_rowptr[idx] = excl;
        g_cursor[idx] = excl;
        if (idx == NN - 1) g_rowptr[NN] = base + incl;
    }
}

__global__ void scatter_kernel(const int* __restrict__ ei) {
    int e = blockIdx.x * 256 + threadIdx.x;
    if (e < EE) {
        int s = ei[e], d = ei[EE + e];
        int p = atomicAdd(&g_cursor[d], 1);
        g_src[p] = s;
    } else if (e < ETOT) {
        int v = e - EE;
        int p = atomicAdd(&g_cursor[v], 1);
        g_src[p] = v;
    }
}

// ---------------- GEMM (FFMA2) + fused attn scalars (R10 proven form) -------
#define AS_LD 132   // padded row stride (floats), div-4 for STS.128
__global__ __launch_bounds__(256, 2)
void gemm_kernel(const float* __restrict__ Aext, int layer,
                 const float* __restrict__ Wm,
                 const float* __restrict__ a_s,
                 const float* __restrict__ a_d) {
    __shared__ float As[128 * AS_LD];   // row-major [r][k]
    __shared__ float Bs[128 * 64];      // [k][c]
    const float* A = (layer == 0) ? Aext : g_x1;
    float* ai = (layer == 0) ? g_ai : g_ai2;
    float* aj = (layer == 0) ? g_aj : g_aj2;

    const int row0 = blockIdx.x * 128;
    const int bx = blockIdx.y;          // 0..3, 64-col tile
    const int t = threadIdx.x;

    const float4* A4 = (const float4*)A;
    for (int i = t; i < 128 * 32; i += 256) {
        int r = i >> 5, k4 = i & 31;
        int gr = row0 + r;
        float4 v = (gr < NN) ? A4[(size_t)gr * 32 + k4]
                             : make_float4(0.f, 0.f, 0.f, 0.f);
        ((float4*)(As + r * AS_LD))[k4] = v;
    }
    const float4* W4 = (const float4*)Wm;
    float4* Bs4 = (float4*)Bs;
    for (int i = t; i < 128 * 16; i += 256) {
        int r = i >> 4, c4 = i & 15;
        Bs4[i] = W4[(size_t)r * 64 + bx * 16 + c4];
    }
    __syncthreads();

    const int ty = t >> 4, tx = t & 15;
    const int r0 = ty * 8, c0 = tx * 4;

    unsigned long long acc[4][4] = {};

#pragma unroll 4
    for (int k = 0; k < 128; k++) {
        float a[8];
#pragma unroll
        for (int u = 0; u < 8; u++) a[u] = As[(r0 + u) * AS_LD + k];
        unsigned long long pa[4];
#pragma unroll
        for (int p = 0; p < 4; p++) PACK2(pa[p], a[2 * p], a[2 * p + 1]);

        float4 bv = Bs4[k * 16 + tx];
        unsigned long long bb[4];
        PACK2(bb[0], bv.x, bv.x);
        PACK2(bb[1], bv.y, bv.y);
        PACK2(bb[2], bv.z, bv.z);
        PACK2(bb[3], bv.w, bv.w);

#pragma unroll
        for (int p = 0; p < 4; p++) {
#pragma unroll
            for (int c = 0; c < 4; c++) FFMA2(acc[p][c], pa[p], bb[c]);
        }
    }

    // epilogue: store xp tile + fused attention partial dots
    const int h = bx >> 1;                       // head for this col tile
    const int c128 = (bx & 1) * 64 + c0;         // col within head
    const float4 as4 = *(const float4*)(a_s + h * CC + c128);
    const float4 ad4 = *(const float4*)(a_d + h * CC + c128);

    float4* out4 = (float4*)g_xp;
    const int colq = (bx * 64 + c0) >> 2;
    float aiv[8], ajv[8];
#pragma unroll
    for (int p = 0; p < 4; p++) {
        float lo0, hi0, lo1, hi1, lo2, hi2, lo3, hi3;
        UNPACK2(lo0, hi0, acc[p][0]);
        UNPACK2(lo1, hi1, acc[p][1]);
        UNPACK2(lo2, hi2, acc[p][2]);
        UNPACK2(lo3, hi3, acc[p][3]);
        int gra = row0 + r0 + 2 * p;
        int grb = gra + 1;
        if (gra < NN) out4[(size_t)gra * 64 + colq] = make_float4(lo0, lo1, lo2, lo3);
        if (grb < NN) out4[(size_t)grb * 64 + colq] = make_float4(hi0, hi1, hi2, hi3);
        aiv[2 * p]     = lo0 * as4.x + lo1 * as4.y + lo2 * as4.z + lo3 * as4.w;
        aiv[2 * p + 1] = hi0 * as4.x + hi1 * as4.y + hi2 * as4.z + hi3 * as4.w;
        ajv[2 * p]     = lo0 * ad4.x + lo1 * ad4.y + lo2 * ad4.z + lo3 * ad4.w;
        ajv[2 * p + 1] = hi0 * ad4.x + hi1 * ad4.y + hi2 * ad4.z + hi3 * ad4.w;
    }
#pragma unroll
    for (int u = 0; u < 8; u++) {
#pragma unroll
        for (int off = 8; off > 0; off >>= 1) {
            aiv[u] += __shfl_down_sync(0xffffffffu, aiv[u], off, 16);
            ajv[u] += __shfl_down_sync(0xffffffffu, ajv[u], off, 16);
        }
    }
    if (tx == 0) {
#pragma unroll
        for (int u = 0; u < 8; u++) {
            int gr = row0 + r0 + u;
            if (gr < NN) {
                atomicAdd(&ai[2 * gr + h], aiv[u]);
                atomicAdd(&aj[2 * gr + h], ajv[u]);
            }
        }
    }
}

// ---------------- fused softmax + aggregation: block per dst node -----------
// Phase A (warp 0): softmax weights into smem. Phase B (all): 4-slot gather.
// mode 0 (layer 1): post -> g_x1 only.  mode 1 (layer 2): g_pre + ext_post.
__global__ void aggregate_kernel(int layer, const float* __restrict__ bias,
                                 float* __restrict__ ext_post, int mode) {
    const int v = blockIdx.x;
    const int t = threadIdx.x;
    const int lane = t & 31;
    __shared__ float4 s_ews[SMAX];   // (w0, w1, src-bits, 0)
    __shared__ float4 red[256];

    const float* ai = (layer == 0) ? g_ai : g_ai2;
    const float* aj = (layer == 0) ? g_aj : g_aj2;
    int beg = g_rowptr[v], deg = g_rowptr[v + 1] - beg;

    // -------- Phase A: warp 0 computes normalized weights into smem --------
    if (t < 32) {
        float ajv0 = aj[2 * v], ajv1 = aj[2 * v + 1];
        int s0 = 0;
        float e0r = -1e30f, e1r = -1e30f;
        if (lane < deg) {
            s0 = __ldg(&g_src[beg + lane]);
            float e0 = ai[2 * s0] + ajv0;     e0r = e0 > 0.f ? e0 : 0.2f * e0;
            float e1 = ai[2 * s0 + 1] + ajv1; e1r = e1 > 0.f ? e1 : 0.2f * e1;
        }
        float m0 = e0r, m1 = e1r;
        for (int i = 32 + lane; i < deg; i += 32) {
            int s = __ldg(&g_src[beg + i]);
            float e0 = ai[2 * s] + ajv0;     e0 = e0 > 0.f ? e0 : 0.2f * e0;
            float e1 = ai[2 * s + 1] + ajv1; e1 = e1 > 0.f ? e1 : 0.2f * e1;
            m0 = fmaxf(m0, e0); m1 = fmaxf(m1, e1);
        }
#pragma unroll
        for (int o = 16; o > 0; o >>= 1) {
            m0 = fmaxf(m0, __shfl_xor_sync(0xffffffff, m0, o));
            m1 = fmaxf(m1, __shfl_xor_sync(0xffffffff, m1, o));
        }
        float d0 = (lane < deg) ? __expf(e0r - m0) : 0.f;
        float d1 = (lane < deg) ? __expf(e1r - m1) : 0.f;
        for (int i = 32 + lane; i < deg; i += 32) {
            int s = __ldg(&g_src[beg + i]);
            float e0 = ai[2 * s] + ajv0;     e0 = e0 > 0.f ? e0 : 0.2f * e0;
            float e1 = ai[2 * s + 1] + ajv1; e1 = e1 > 0.f ? e1 : 0.2f * e1;
            d0 += __expf(e0 - m0); d1 += __expf(e1 - m1);
        }
#pragma unroll
        for (int o = 16; o > 0; o >>= 1) {
            d0 += __shfl_xor_sync(0xffffffff, d0, o);
            d1 += __shfl_xor_sync(0xffffffff, d1, o);
        }
        float inv_d0 = 1.f / (d0 + 1e-16f);
        float inv_d1 = 1.f / (d1 + 1e-16f);

        if (lane < deg) {
            float w0 = __expf(e0r - m0) * inv_d0;
            float w1 = __expf(e1r - m1) * inv_d1;
            s_ews[lane] = make_float4(w0, w1, __int_as_float(s0), 0.f);
        }
        for (int i = 32 + lane; i < deg && i < SMAX; i += 32) {
            int s = __ldg(&g_src[beg + i]);
            float e0 = ai[2 * s] + ajv0;     e0 = e0 > 0.f ? e0 : 0.2f * e0;
            float e1 = ai[2 * s + 1] + ajv1; e1 = e1 > 0.f ? e1 : 0.2f * e1;
            float w0 = __expf(e0 - m0) * inv_d0;
            float w1 = __expf(e1 - m1) * inv_d1;
            s_ews[i] = make_float4(w0, w1, __int_as_float(s), 0.f);
        }
    }
    __syncthreads();

    // -------- Phase B: 4 slots x 64 float4-lanes gather (proven config) ----
    const int j = t >> 6;        // edge slot within group of 4
    const int q = t & 63;        // float4 lane (256 floats per row)
    const int head = q >> 5;     // warp-uniform
    const float4* xp4 = (const float4*)g_xp;
    int degc = min(deg, SMAX);

    float4 acc = make_float4(0.f, 0.f, 0.f, 0.f);
    float4 acc2 = make_float4(0.f, 0.f, 0.f, 0.f);
    int i = j;
    for (; i + 4 < degc; i += 8) {   // two independent chains
        float4 ewa = s_ews[i];
        float4 ewb = s_ews[i + 4];
        float wa = head ? ewa.y : ewa.x;
        float wb = head ? ewb.y : ewb.x;
        float4 xa = xp4[(size_t)__float_as_int(ewa.z) * 64 + q];
        float4 xb = xp4[(size_t)__float_as_int(ewb.z) * 64 + q];
        acc.x += wa * xa.x; acc.y += wa * xa.y;
        acc.z += wa * xa.z; acc.w += wa * xa.w;
        acc2.x += wb * xb.x; acc2.y += wb * xb.y;
        acc2.z += wb * xb.z; acc2.w += wb * xb.w;
    }
    for (; i < degc; i += 4) {
        float4 ew = s_ews[i];
        float w = head ? ew.y : ew.x;
        float4 xv = xp4[(size_t)__float_as_int(ew.z) * 64 + q];
        acc.x += w * xv.x; acc.y += w * xv.y;
        acc.z += w * xv.z; acc.w += w * xv.w;
    }
    acc.x += acc2.x; acc.y += acc2.y; acc.z += acc2.z; acc.w += acc2.w;

    red[t] = acc;
    __syncthreads();
    if (t < 64) {
        float4 a = red[t], b = red[64 + t], c = red[128 + t], d = red[192 + t];
        a.x += b.x + c.x + d.x; a.y += b.y + c.y + d.y;
        a.z += b.z + c.z + d.z; a.w += b.w + c.w + d.w;
        red[t] = a;
    }
    __syncthreads();
    if (t < 32) {
        float4 h0 = red[t], h1 = red[32 + t];
        float4 bb = __ldg(&((const float4*)bias)[t]);
        float4 o;
        o.x = (h0.x + h1.x) * 0.5f + bb.x;
        o.y = (h0.y + h1.y) * 0.5f + bb.y;
        o.z = (h0.z + h1.z) * 0.5f + bb.z;
        o.w = (h0.w + h1.w) * 0.5f + bb.w;
        float4 p;
        p.x = o.x > 0.f ? o.x : 0.01f * o.x;
        p.y = o.y > 0.f ? o.y : 0.01f * o.y;
        p.z = o.z > 0.f ? o.z : 0.01f * o.z;
        p.w = o.w > 0.f ? o.w : 0.01f * o.w;
        if (mode == 0) {
            ((float4*)g_x1)[(size_t)v * 32 + t] = p;
        } else {
            ((float4*)g_pre)[(size_t)v * 32 + t] = o;
            ((float4*)ext_post)[(size_t)v * 32 + t] = p;
        }
    }
}

// ---------------- edge score head -------------------------------------------
__global__ void score_kernel(const int* __restrict__ ei,
                             const float* __restrict__ ea,
                             float* __restrict__ out) {
    int gw = (blockIdx.x * 256 + threadIdx.x) >> 5;
    if (gw >= EE) return;
    int lane = threadIdx.x & 31;
    int s = ei[gw], d = ei[EE + gw];
    const float4* xs = (const float4*)(g_pre + (size_t)s * 128);
    const float4* xd = (const float4*)(g_pre + (size_t)d * 128);
    const float4* e4 = (const float4*)(ea + (size_t)gw * 128);
    float4 a = xs[lane], b = xd[lane], c = e4[lane];
    float acc = a.x * b.x * c.x + a.y * b.y * c.y + a.z * b.z * c.z + a.w * b.w * c.w;
#pragma unroll
    for (int o = 16; o > 0; o >>= 1) acc += __shfl_xor_sync(0xffffffff, acc, o);
    if (lane == 0) out[gw] = 1.f / (1.f + __expf(-acc));
}

// ---------------- launch -----------------------------------------------------
extern "C" void kernel_launch(void* const* d_in, const int* in_sizes, int n_in,
                              void* d_out, int out_size) {
    const float* x   = (const float*)d_in[0];
    const int*   ei  = (const int*)d_in[1];
    const float* ea  = (const float*)d_in[2];
    const float* W1  = (const float*)d_in[3];
    const float* as1 = (const float*)d_in[4];
    const float* ad1 = (const float*)d_in[5];
    const float* b1  = (const float*)d_in[6];
    const float* W2  = (const float*)d_in[7];
    const float* as2 = (const float*)d_in[8];
    const float* ad2 = (const float*)d_in[9];
    const float* b2  = (const float*)d_in[10];

    float* out_x  = (float*)d_out;
    float* out_sc = out_x + (size_t)NN * CC;

    // CSR build (topology shared by both layers) + zero attn — single stream
    init_kernel<<<(NN * HH + 255) / 256, 256>>>();
    count_kernel<<<(EE + 255) / 256, 256>>>(ei);
    scan_pass1<<<NBLK, 256>>>();
    scan_pass2<<<1, 256>>>();
    scan_pass3<<<NBLK, 256>>>();
    scatter_kernel<<<(ETOT + 255) / 256, 256>>>(ei);

    dim3 ggrid((NN + 127) / 128, 4);

    // layer 1
    gemm_kernel<<<ggrid, 256>>>(x, 0, W1, as1, ad1);
    aggregate_kernel<<<NN, 256>>>(0, b1, nullptr, 0);   // -> g_x1

    // layer 2
    gemm_kernel<<<ggrid, 256>>>(nullptr, 1, W2, as2, ad2);
    aggregate_kernel<<<NN, 256>>>(1, b2, out_x, 1);     // -> g_pre, out_x

    // edge scores from layer-2 pre-activation
    score_kernel<<<(EE * 32 + 255) / 256, 256>>>(ei, ea, out_sc);
}

// round 16
// speedup vs baseline: 1.1171x; 1.1171x over previous
#include <cuda_runtime.h>
#include <cuda_bf16.h>
#include <cuda_fp16.h>

#define NN 50000
#define EE 800000
#define CC 128
#define HH 2
#define ETOT (EE + NN)   // edges + self loops
#define NBLK 196         // ceil(NN/256)

// packed f32x2 helpers (Blackwell; ptxas never auto-emits FFMA2)
#define FFMA2(d, a, b) asm("fma.rn.f32x2 %0, %1, %2, %0;" : "+l"(d) : "l"(a), "l"(b))
#define PACK2(d, lo, hi) asm("mov.b64 %0, {%1, %2};" : "=l"(d) \
    : "r"(__float_as_uint(lo)), "r"(__float_as_uint(hi)))
#define UNPACK2(lo, hi, d) do { unsigned int _ul, _uh; \
    asm("mov.b64 {%0, %1}, %2;" : "=r"(_ul), "=r"(_uh) : "l"(d)); \
    lo = __uint_as_float(_ul); hi = __uint_as_float(_uh); } while (0)

// ---------------- scratch (device globals; no allocation allowed) -----------
__device__ __half  g_xph[(size_t)NN * HH * CC]; // [N][H][C] projected (fp16)
__device__ float  g_ai[NN * HH];                // layer-1 src attention scalars
__device__ float  g_aj[NN * HH];                // layer-1 dst attention scalars
__device__ float  g_ai2[NN * HH];               // layer-2 src attention scalars
__device__ float  g_aj2[NN * HH];               // layer-2 dst attention scalars
__device__ float  g_x1[(size_t)NN * CC];        // layer-1 post-activation
__device__ float  g_pre[(size_t)NN * CC];       // layer-2 pre-activation (score)
__device__ int    g_cnt[NN];
__device__ int    g_rowptr[NN + 1];
__device__ int    g_cursor[NN];
__device__ int    g_src[ETOT];                  // CSR-by-dst: src node per slot
__device__ float4 g_ew[ETOT];                   // per-slot (w0, w1, src-bits, 0)
__device__ int    g_bsum[NBLK];
__device__ int    g_boff[NBLK];

// ---------------- init: cnt=1, zero all attn scalars ------------------------
__global__ void init_kernel() {
    int i = blockIdx.x * 256 + threadIdx.x;
    if (i < NN) g_cnt[i] = 1;   // self loop
    if (i < NN * HH) {
        g_ai[i] = 0.f;  g_aj[i] = 0.f;
        g_ai2[i] = 0.f; g_aj2[i] = 0.f;
    }
}

__global__ void count_kernel(const int* __restrict__ ei) {
    int e = blockIdx.x * 256 + threadIdx.x;
    if (e < EE) atomicAdd(&g_cnt[ei[EE + e]], 1);
}

// ---------------- 3-phase scan ----------------------------------------------
__global__ void scan_pass1() {
    __shared__ int sh[256];
    int idx = blockIdx.x * 256 + threadIdx.x;
    sh[threadIdx.x] = (idx < NN) ? g_cnt[idx] : 0;
    __syncthreads();
    for (int s = 128; s > 0; s >>= 1) {
        if (threadIdx.x < s) sh[threadIdx.x] += sh[threadIdx.x + s];
        __syncthreads();
    }
    if (threadIdx.x == 0) g_bsum[blockIdx.x] = sh[0];
}

__global__ void scan_pass2() {
    __shared__ int sh[256];
    int t = threadIdx.x;
    int v = (t < NBLK) ? g_bsum[t] : 0;
    sh[t] = v;
    __syncthreads();
    for (int off = 1; off < 256; off <<= 1) {
        int add = (t >= off) ? sh[t - off] : 0;
        __syncthreads();
        sh[t] += add;
        __syncthreads();
    }
    if (t < NBLK) g_boff[t] = sh[t] - v;   // exclusive
}

__global__ void scan_pass3() {
    __shared__ int sh[256];
    int b = blockIdx.x, t = threadIdx.x;
    int idx = b * 256 + t;
    int v = (idx < NN) ? g_cnt[idx] : 0;
    sh[t] = v;
    __syncthreads();
    for (int off = 1; off < 256; off <<= 1) {
        int add = (t >= off) ? sh[t - off] : 0;
        __syncthreads();
        sh[t] += add;
        __syncthreads();
    }
    int incl = sh[t];
    int base = g_boff[b];
    if (idx < NN) {
        int excl = base + incl - v;
        g_rowptr[idx] = excl;
        g_cursor[idx] = excl;
        if (idx == NN - 1) g_rowptr[NN] = base + incl;
    }
}

__global__ void scatter_kernel(const int* __restrict__ ei) {
    int e = blockIdx.x * 256 + threadIdx.x;
    if (e < EE) {
        int s = ei[e], d = ei[EE + e];
        int p = atomicAdd(&g_cursor[d], 1);
        g_src[p] = s;
    } else if (e < ETOT) {
        int v = e - EE;
        int p = atomicAdd(&g_cursor[v], 1);
        g_src[p] = v;
    }
}

// ---------------- GEMM (FFMA2) + fused attn scalars, fp16 xp output ---------
#define AS_LD 132   // padded row stride (floats), div-4 for STS.128
__global__ __launch_bounds__(256, 2)
void gemm_kernel(const float* __restrict__ Aext, int layer,
                 const float* __restrict__ Wm,
                 const float* __restrict__ a_s,
                 const float* __restrict__ a_d) {
    __shared__ float As[128 * AS_LD];   // row-major [r][k]
    __shared__ float Bs[128 * 64];      // [k][c]
    const float* A = (layer == 0) ? Aext : g_x1;
    float* ai = (layer == 0) ? g_ai : g_ai2;
    float* aj = (layer == 0) ? g_aj : g_aj2;

    const int row0 = blockIdx.x * 128;
    const int bx = blockIdx.y;          // 0..3, 64-col tile
    const int t = threadIdx.x;

    const float4* A4 = (const float4*)A;
    for (int i = t; i < 128 * 32; i += 256) {
        int r = i >> 5, k4 = i & 31;
        int gr = row0 + r;
        float4 v = (gr < NN) ? A4[(size_t)gr * 32 + k4]
                             : make_float4(0.f, 0.f, 0.f, 0.f);
        ((float4*)(As + r * AS_LD))[k4] = v;
    }
    const float4* W4 = (const float4*)Wm;
    float4* Bs4 = (float4*)Bs;
    for (int i = t; i < 128 * 16; i += 256) {
        int r = i >> 4, c4 = i & 15;
        Bs4[i] = W4[(size_t)r * 64 + bx * 16 + c4];
    }
    __syncthreads();

    const int ty = t >> 4, tx = t & 15;
    const int r0 = ty * 8, c0 = tx * 4;

    unsigned long long acc[4][4] = {};

#pragma unroll 4
    for (int k = 0; k < 128; k++) {
        float a[8];
#pragma unroll
        for (int u = 0; u < 8; u++) a[u] = As[(r0 + u) * AS_LD + k];
        unsigned long long pa[4];
#pragma unroll
        for (int p = 0; p < 4; p++) PACK2(pa[p], a[2 * p], a[2 * p + 1]);

        float4 bv = Bs4[k * 16 + tx];
        unsigned long long bb[4];
        PACK2(bb[0], bv.x, bv.x);
        PACK2(bb[1], bv.y, bv.y);
        PACK2(bb[2], bv.z, bv.z);
        PACK2(bb[3], bv.w, bv.w);

#pragma unroll
        for (int p = 0; p < 4; p++) {
#pragma unroll
            for (int c = 0; c < 4; c++) FFMA2(acc[p][c], pa[p], bb[c]);
        }
    }

    // epilogue: store fp16 xp tile + fused attention partial dots (fp32)
    const int h = bx >> 1;                       // head for this col tile
    const int c128 = (bx & 1) * 64 + c0;         // col within head
    const float4 as4 = *(const float4*)(a_s + h * CC + c128);
    const float4 ad4 = *(const float4*)(a_d + h * CC + c128);

    uint2* outh = (uint2*)g_xph;                 // half4 per uint2
    const int colq = (bx * 64 + c0) >> 2;        // half4 index within 256-wide row
    float aiv[8], ajv[8];
#pragma unroll
    for (int p = 0; p < 4; p++) {
        float lo0, hi0, lo1, hi1, lo2, hi2, lo3, hi3;
        UNPACK2(lo0, hi0, acc[p][0]);
        UNPACK2(lo1, hi1, acc[p][1]);
        UNPACK2(lo2, hi2, acc[p][2]);
        UNPACK2(lo3, hi3, acc[p][3]);
        int gra = row0 + r0 + 2 * p;
        int grb = gra + 1;
        if (gra < NN) {
            __half2 pA = __floats2half2_rn(lo0, lo1);
            __half2 pB = __floats2half2_rn(lo2, lo3);
            uint2 u;
            u.x = *(unsigned int*)&pA;
            u.y = *(unsigned int*)&pB;
            outh[(size_t)gra * 64 + colq] = u;
        }
        if (grb < NN) {
            __half2 pA = __floats2half2_rn(hi0, hi1);
            __half2 pB = __floats2half2_rn(hi2, hi3);
            uint2 u;
            u.x = *(unsigned int*)&pA;
            u.y = *(unsigned int*)&pB;
            outh[(size_t)grb * 64 + colq] = u;
        }
        aiv[2 * p]     = lo0 * as4.x + lo1 * as4.y + lo2 * as4.z + lo3 * as4.w;
        aiv[2 * p + 1] = hi0 * as4.x + hi1 * as4.y + hi2 * as4.z + hi3 * as4.w;
        ajv[2 * p]     = lo0 * ad4.x + lo1 * ad4.y + lo2 * ad4.z + lo3 * ad4.w;
        ajv[2 * p + 1] = hi0 * ad4.x + hi1 * ad4.y + hi2 * ad4.z + hi3 * ad4.w;
    }
#pragma unroll
    for (int u = 0; u < 8; u++) {
#pragma unroll
        for (int off = 8; off > 0; off >>= 1) {
            aiv[u] += __shfl_down_sync(0xffffffffu, aiv[u], off, 16);
            ajv[u] += __shfl_down_sync(0xffffffffu, ajv[u], off, 16);
        }
    }
    if (tx == 0) {
#pragma unroll
        for (int u = 0; u < 8; u++) {
            int gr = row0 + r0 + u;
            if (gr < NN) {
                atomicAdd(&ai[2 * gr + h], aiv[u]);
                atomicAdd(&aj[2 * gr + h], ajv[u]);
            }
        }
    }
}

// ---------------- softmax weights: warp per dst node (register-cached) ------
__global__ void weights_kernel(int layer) {
    int gw = (blockIdx.x * 256 + threadIdx.x) >> 5;
    int lane = threadIdx.x & 31;
    if (gw >= NN) return;
    const int v = gw;
    const float* ai = (layer == 0) ? g_ai : g_ai2;
    const float* aj = (layer == 0) ? g_aj : g_aj2;
    int beg = g_rowptr[v], deg = g_rowptr[v + 1] - beg;
    float ajv0 = aj[2 * v], ajv1 = aj[2 * v + 1];

    int s0 = 0;
    float e0r = -1e30f, e1r = -1e30f;
    if (lane < deg) {
        s0 = __ldg(&g_src[beg + lane]);
        float e0 = ai[2 * s0] + ajv0;     e0r = e0 > 0.f ? e0 : 0.2f * e0;
        float e1 = ai[2 * s0 + 1] + ajv1; e1r = e1 > 0.f ? e1 : 0.2f * e1;
    }
    float m0 = e0r, m1 = e1r;
    for (int i = 32 + lane; i < deg; i += 32) {
        int s = __ldg(&g_src[beg + i]);
        float e0 = ai[2 * s] + ajv0;     e0 = e0 > 0.f ? e0 : 0.2f * e0;
        float e1 = ai[2 * s + 1] + ajv1; e1 = e1 > 0.f ? e1 : 0.2f * e1;
        m0 = fmaxf(m0, e0); m1 = fmaxf(m1, e1);
    }
#pragma unroll
    for (int o = 16; o > 0; o >>= 1) {
        m0 = fmaxf(m0, __shfl_xor_sync(0xffffffff, m0, o));
        m1 = fmaxf(m1, __shfl_xor_sync(0xffffffff, m1, o));
    }

    float d0 = (lane < deg) ? __expf(e0r - m0) : 0.f;
    float d1 = (lane < deg) ? __expf(e1r - m1) : 0.f;
    for (int i = 32 + lane; i < deg; i += 32) {
        int s = __ldg(&g_src[beg + i]);
        float e0 = ai[2 * s] + ajv0;     e0 = e0 > 0.f ? e0 : 0.2f * e0;
        float e1 = ai[2 * s + 1] + ajv1; e1 = e1 > 0.f ? e1 : 0.2f * e1;
        d0 += __expf(e0 - m0); d1 += __expf(e1 - m1);
    }
#pragma unroll
    for (int o = 16; o > 0; o >>= 1) {
        d0 += __shfl_xor_sync(0xffffffff, d0, o);
        d1 += __shfl_xor_sync(0xffffffff, d1, o);
    }
    float inv_d0 = 1.f / (d0 + 1e-16f);
    float inv_d1 = 1.f / (d1 + 1e-16f);

    if (lane < deg) {
        float w0 = __expf(e0r - m0) * inv_d0;
        float w1 = __expf(e1r - m1) * inv_d1;
        g_ew[beg + lane] = make_float4(w0, w1, __int_as_float(s0), 0.f);
    }
    for (int i = 32 + lane; i < deg; i += 32) {
        int s = __ldg(&g_src[beg + i]);
        float e0 = ai[2 * s] + ajv0;     e0 = e0 > 0.f ? e0 : 0.2f * e0;
        float e1 = ai[2 * s + 1] + ajv1; e1 = e1 > 0.f ? e1 : 0.2f * e1;
        float w0 = __expf(e0 - m0) * inv_d0;
        float w1 = __expf(e1 - m1) * inv_d1;
        g_ew[beg + i] = make_float4(w0, w1, __int_as_float(s), 0.f);
    }
}

// ---------------- aggregation: block per dst, 4 edges x 64 half4-lanes ------
// mode 0 (layer 1): post -> g_x1 only.  mode 1 (layer 2): g_pre + ext_post.
__global__ void aggregate_kernel(const float* __restrict__ bias,
                                 float* __restrict__ ext_post, int mode) {
    const int v = blockIdx.x;
    const int t = threadIdx.x;
    const int j = t >> 6;        // edge slot within group of 4
    const int q = t & 63;        // half4 lane (256 halves per row)
    const int head = q >> 5;     // q<32 -> head0, else head1 (warp-uniform)
    __shared__ float4 red[256];

    int beg = g_rowptr[v], deg = g_rowptr[v + 1] - beg;
    const uint2* xph2 = (const uint2*)g_xph;

    float4 acc = make_float4(0.f, 0.f, 0.f, 0.f);
    float4 acc2 = make_float4(0.f, 0.f, 0.f, 0.f);
    int i = j;
    for (; i + 4 < deg; i += 8) {   // two independent chains
        float4 ewa = __ldg(&g_ew[beg + i]);
        float4 ewb = __ldg(&g_ew[beg + i + 4]);
        float wa = head ? ewa.y : ewa.x;
        float wb = head ? ewb.y : ewb.x;
        uint2 ua = xph2[(size_t)__float_as_int(ewa.z) * 64 + q];
        uint2 ub = xph2[(size_t)__float_as_int(ewb.z) * 64 + q];
        float2 a01 = __half22float2(*(__half2*)&ua.x);
        float2 a23 = __half22float2(*(__half2*)&ua.y);
        float2 b01 = __half22float2(*(__half2*)&ub.x);
        float2 b23 = __half22float2(*(__half2*)&ub.y);
        acc.x += wa * a01.x; acc.y += wa * a01.y;
        acc.z += wa * a23.x; acc.w += wa * a23.y;
        acc2.x += wb * b01.x; acc2.y += wb * b01.y;
        acc2.z += wb * b23.x; acc2.w += wb * b23.y;
    }
    for (; i < deg; i += 4) {
        float4 ew = __ldg(&g_ew[beg + i]);
        float w = head ? ew.y : ew.x;
        uint2 u = xph2[(size_t)__float_as_int(ew.z) * 64 + q];
        float2 a01 = __half22float2(*(__half2*)&u.x);
        float2 a23 = __half22float2(*(__half2*)&u.y);
        acc.x += w * a01.x; acc.y += w * a01.y;
        acc.z += w * a23.x; acc.w += w * a23.y;
    }
    acc.x += acc2.x; acc.y += acc2.y; acc.z += acc2.z; acc.w += acc2.w;

    red[t] = acc;
    __syncthreads();
    if (t < 64) {
        float4 a = red[t], b = red[64 + t], c = red[128 + t], d = red[192 + t];
        a.x += b.x + c.x + d.x; a.y += b.y + c.y + d.y;
        a.z += b.z + c.z + d.z; a.w += b.w + c.w + d.w;
        red[t] = a;
    }
    __syncthreads();
    if (t < 32) {
        float4 h0 = red[t], h1 = red[32 + t];
        float4 bb = __ldg(&((const float4*)bias)[t]);
        float4 o;
        o.x = (h0.x + h1.x) * 0.5f + bb.x;
        o.y = (h0.y + h1.y) * 0.5f + bb.y;
        o.z = (h0.z + h1.z) * 0.5f + bb.z;
        o.w = (h0.w + h1.w) * 0.5f + bb.w;
        float4 p;
        p.x = o.x > 0.f ? o.x : 0.01f * o.x;
        p.y = o.y > 0.f ? o.y : 0.01f * o.y;
        p.z = o.z > 0.f ? o.z : 0.01f * o.z;
        p.w = o.w > 0.f ? o.w : 0.01f * o.w;
        if (mode == 0) {
            ((float4*)g_x1)[(size_t)v * 32 + t] = p;
        } else {
            ((float4*)g_pre)[(size_t)v * 32 + t] = o;
            ((float4*)ext_post)[(size_t)v * 32 + t] = p;
        }
    }
}

// ---------------- edge score head -------------------------------------------
__global__ void score_kernel(const int* __restrict__ ei,
                             const float* __restrict__ ea,
                             float* __restrict__ out) {
    int gw = (blockIdx.x * 256 + threadIdx.x) >> 5;
    if (gw >= EE) return;
    int lane = threadIdx.x & 31;
    int s = ei[gw], d = ei[EE + gw];
    const float4* xs = (const float4*)(g_pre + (size_t)s * 128);
    const float4* xd = (const float4*)(g_pre + (size_t)d * 128);
    const float4* e4 = (const float4*)(ea + (size_t)gw * 128);
    float4 a = xs[lane], b = xd[lane], c = e4[lane];
    float acc = a.x * b.x * c.x + a.y * b.y * c.y + a.z * b.z * c.z + a.w * b.w * c.w;
#pragma unroll
    for (int o = 16; o > 0; o >>= 1) acc += __shfl_xor_sync(0xffffffff, acc, o);
    if (lane == 0) out[gw] = 1.f / (1.f + __expf(-acc));
}

// ---------------- launch -----------------------------------------------------
extern "C" void kernel_launch(void* const* d_in, const int* in_sizes, int n_in,
                              void* d_out, int out_size) {
    const float* x   = (const float*)d_in[0];
    const int*   ei  = (const int*)d_in[1];
    const float* ea  = (const float*)d_in[2];
    const float* W1  = (const float*)d_in[3];
    const float* as1 = (const float*)d_in[4];
    const float* ad1 = (const float*)d_in[5];
    const float* b1  = (const float*)d_in[6];
    const float* W2  = (const float*)d_in[7];
    const float* as2 = (const float*)d_in[8];
    const float* ad2 = (const float*)d_in[9];
    const float* b2  = (const float*)d_in[10];

    float* out_x  = (float*)d_out;
    float* out_sc = out_x + (size_t)NN * CC;

    // CSR build (topology shared by both layers) + zero attn — single stream
    init_kernel<<<(NN * HH + 255) / 256, 256>>>();
    count_kernel<<<(EE + 255) / 256, 256>>>(ei);
    scan_pass1<<<NBLK, 256>>>();
    scan_pass2<<<1, 256>>>();
    scan_pass3<<<NBLK, 256>>>();
    scatter_kernel<<<(ETOT + 255) / 256, 256>>>(ei);

    dim3 ggrid((NN + 127) / 128, 4);
    int wblocks = (NN * 32 + 255) / 256;

    // layer 1
    gemm_kernel<<<ggrid, 256>>>(x, 0, W1, as1, ad1);
    weights_kernel<<<wblocks, 256>>>(0);
    aggregate_kernel<<<NN, 256>>>(b1, nullptr, 0);   // -> g_x1

    // layer 2
    gemm_kernel<<<ggrid, 256>>>(nullptr, 1, W2, as2, ad2);
    weights_kernel<<<wblocks, 256>>>(1);
    aggregate_kernel<<<NN, 256>>>(b2, out_x, 1);     // -> g_pre, out_x

    // edge scores from layer-2 pre-activation
    score_kernel<<<(EE * 32 + 255) / 256, 256>>>(ei, ea, out_sc);
}

// round 17
// speedup vs baseline: 1.1284x; 1.0101x over previous
#include <cuda_runtime.h>
#include <cuda_bf16.h>
#include <cuda_fp16.h>

#define NN 50000
#define EE 800000
#define CC 128
#define HH 2
#define ETOT (EE + NN)   // edges + self loops
#define NBLK 196         // ceil(NN/256)

// packed f32x2 helpers (Blackwell; ptxas never auto-emits FFMA2)
#define FFMA2(d, a, b) asm("fma.rn.f32x2 %0, %1, %2, %0;" : "+l"(d) : "l"(a), "l"(b))
#define PACK2(d, lo, hi) asm("mov.b64 %0, {%1, %2};" : "=l"(d) \
    : "r"(__float_as_uint(lo)), "r"(__float_as_uint(hi)))
#define UNPACK2(lo, hi, d) do { unsigned int _ul, _uh; \
    asm("mov.b64 {%0, %1}, %2;" : "=r"(_ul), "=r"(_uh) : "l"(d)); \
    lo = __uint_as_float(_ul); hi = __uint_as_float(_uh); } while (0)

// ---------------- scratch (device globals; no allocation allowed) -----------
__device__ __half  g_xph[(size_t)NN * HH * CC]; // [N][H][C] projected (fp16)
__device__ __half  g_preh[(size_t)NN * CC];     // layer-2 pre-activation (fp16)
__device__ float  g_ai[NN * HH];                // layer-1 src attention scalars
__device__ float  g_aj[NN * HH];                // layer-1 dst attention scalars
__device__ float  g_ai2[NN * HH];               // layer-2 src attention scalars
__device__ float  g_aj2[NN * HH];               // layer-2 dst attention scalars
__device__ float  g_x1[(size_t)NN * CC];        // layer-1 post-activation
__device__ int    g_cnt[NN];
__device__ int    g_rowptr[NN + 1];
__device__ int    g_cursor[NN];
__device__ int    g_src[ETOT];                  // CSR-by-dst: src node per slot
__device__ float4 g_ew[ETOT];                   // per-slot (w0, w1, src-bits, 0)
__device__ int    g_bsum[NBLK];
__device__ int    g_boff[NBLK];

// ---------------- init: cnt=1, zero all attn scalars ------------------------
__global__ void init_kernel() {
    int i = blockIdx.x * 256 + threadIdx.x;
    if (i < NN) g_cnt[i] = 1;   // self loop
    if (i < NN * HH) {
        g_ai[i] = 0.f;  g_aj[i] = 0.f;
        g_ai2[i] = 0.f; g_aj2[i] = 0.f;
    }
}

__global__ void count_kernel(const int* __restrict__ ei) {
    int e = blockIdx.x * 256 + threadIdx.x;
    if (e < EE) atomicAdd(&g_cnt[ei[EE + e]], 1);
}

// ---------------- 3-phase scan ----------------------------------------------
__global__ void scan_pass1() {
    __shared__ int sh[256];
    int idx = blockIdx.x * 256 + threadIdx.x;
    sh[threadIdx.x] = (idx < NN) ? g_cnt[idx] : 0;
    __syncthreads();
    for (int s = 128; s > 0; s >>= 1) {
        if (threadIdx.x < s) sh[threadIdx.x] += sh[threadIdx.x + s];
        __syncthreads();
    }
    if (threadIdx.x == 0) g_bsum[blockIdx.x] = sh[0];
}

__global__ void scan_pass2() {
    __shared__ int sh[256];
    int t = threadIdx.x;
    int v = (t < NBLK) ? g_bsum[t] : 0;
    sh[t] = v;
    __syncthreads();
    for (int off = 1; off < 256; off <<= 1) {
        int add = (t >= off) ? sh[t - off] : 0;
        __syncthreads();
        sh[t] += add;
        __syncthreads();
    }
    if (t < NBLK) g_boff[t] = sh[t] - v;   // exclusive
}

__global__ void scan_pass3() {
    __shared__ int sh[256];
    int b = blockIdx.x, t = threadIdx.x;
    int idx = b * 256 + t;
    int v = (idx < NN) ? g_cnt[idx] : 0;
    sh[t] = v;
    __syncthreads();
    for (int off = 1; off < 256; off <<= 1) {
        int add = (t >= off) ? sh[t - off] : 0;
        __syncthreads();
        sh[t] += add;
        __syncthreads();
    }
    int incl = sh[t];
    int base = g_boff[b];
    if (idx < NN) {
        int excl = base + incl - v;
        g_rowptr[idx] = excl;
        g_cursor[idx] = excl;
        if (idx == NN - 1) g_rowptr[NN] = base + incl;
    }
}

__global__ void scatter_kernel(const int* __restrict__ ei) {
    int e = blockIdx.x * 256 + threadIdx.x;
    if (e < EE) {
        int s = ei[e], d = ei[EE + e];
        int p = atomicAdd(&g_cursor[d], 1);
        g_src[p] = s;
    } else if (e < ETOT) {
        int v = e - EE;
        int p = atomicAdd(&g_cursor[v], 1);
        g_src[p] = v;
    }
}

// ---------------- GEMM (FFMA2) + fused attn scalars, fp16 xp output ---------
#define AS_LD 132   // padded row stride (floats), div-4 for STS.128
__global__ __launch_bounds__(256, 2)
void gemm_kernel(const float* __restrict__ Aext, int layer,
                 const float* __restrict__ Wm,
                 const float* __restrict__ a_s,
                 const float* __restrict__ a_d) {
    __shared__ float As[128 * AS_LD];   // row-major [r][k]
    __shared__ float Bs[128 * 64];      // [k][c]
    const float* A = (layer == 0) ? Aext : g_x1;
    float* ai = (layer == 0) ? g_ai : g_ai2;
    float* aj = (layer == 0) ? g_aj : g_aj2;

    const int row0 = blockIdx.x * 128;
    const int bx = blockIdx.y;          // 0..3, 64-col tile
    const int t = threadIdx.x;

    const float4* A4 = (const float4*)A;
    for (int i = t; i < 128 * 32; i += 256) {
        int r = i >> 5, k4 = i & 31;
        int gr = row0 + r;
        float4 v = (gr < NN) ? A4[(size_t)gr * 32 + k4]
                             : make_float4(0.f, 0.f, 0.f, 0.f);
        ((float4*)(As + r * AS_LD))[k4] = v;
    }
    const float4* W4 = (const float4*)Wm;
    float4* Bs4 = (float4*)Bs;
    for (int i = t; i < 128 * 16; i += 256) {
        int r = i >> 4, c4 = i & 15;
        Bs4[i] = W4[(size_t)r * 64 + bx * 16 + c4];
    }
    __syncthreads();

    const int ty = t >> 4, tx = t & 15;
    const int r0 = ty * 8, c0 = tx * 4;

    unsigned long long acc[4][4] = {};

#pragma unroll 4
    for (int k = 0; k < 128; k++) {
        float a[8];
#pragma unroll
        for (int u = 0; u < 8; u++) a[u] = As[(r0 + u) * AS_LD + k];
        unsigned long long pa[4];
#pragma unroll
        for (int p = 0; p < 4; p++) PACK2(pa[p], a[2 * p], a[2 * p + 1]);

        float4 bv = Bs4[k * 16 + tx];
        unsigned long long bb[4];
        PACK2(bb[0], bv.x, bv.x);
        PACK2(bb[1], bv.y, bv.y);
        PACK2(bb[2], bv.z, bv.z);
        PACK2(bb[3], bv.w, bv.w);

#pragma unroll
        for (int p = 0; p < 4; p++) {
#pragma unroll
            for (int c = 0; c < 4; c++) FFMA2(acc[p][c], pa[p], bb[c]);
        }
    }

    // epilogue: store fp16 xp tile + fused attention partial dots (fp32)
    const int h = bx >> 1;                       // head for this col tile
    const int c128 = (bx & 1) * 64 + c0;         // col within head
    const float4 as4 = *(const float4*)(a_s + h * CC + c128);
    const float4 ad4 = *(const float4*)(a_d + h * CC + c128);

    uint2* outh = (uint2*)g_xph;                 // half4 per uint2
    const int colq = (bx * 64 + c0) >> 2;        // half4 index within 256-wide row
    float aiv[8], ajv[8];
#pragma unroll
    for (int p = 0; p < 4; p++) {
        float lo0, hi0, lo1, hi1, lo2, hi2, lo3, hi3;
        UNPACK2(lo0, hi0, acc[p][0]);
        UNPACK2(lo1, hi1, acc[p][1]);
        UNPACK2(lo2, hi2, acc[p][2]);
        UNPACK2(lo3, hi3, acc[p][3]);
        int gra = row0 + r0 + 2 * p;
        int grb = gra + 1;
        if (gra < NN) {
            __half2 pA = __floats2half2_rn(lo0, lo1);
            __half2 pB = __floats2half2_rn(lo2, lo3);
            uint2 u;
            u.x = *(unsigned int*)&pA;
            u.y = *(unsigned int*)&pB;
            outh[(size_t)gra * 64 + colq] = u;
        }
        if (grb < NN) {
            __half2 pA = __floats2half2_rn(hi0, hi1);
            __half2 pB = __floats2half2_rn(hi2, hi3);
            uint2 u;
            u.x = *(unsigned int*)&pA;
            u.y = *(unsigned int*)&pB;
            outh[(size_t)grb * 64 + colq] = u;
        }
        aiv[2 * p]     = lo0 * as4.x + lo1 * as4.y + lo2 * as4.z + lo3 * as4.w;
        aiv[2 * p + 1] = hi0 * as4.x + hi1 * as4.y + hi2 * as4.z + hi3 * as4.w;
        ajv[2 * p]     = lo0 * ad4.x + lo1 * ad4.y + lo2 * ad4.z + lo3 * ad4.w;
        ajv[2 * p + 1] = hi0 * ad4.x + hi1 * ad4.y + hi2 * ad4.z + hi3 * ad4.w;
    }
#pragma unroll
    for (int u = 0; u < 8; u++) {
#pragma unroll
        for (int off = 8; off > 0; off >>= 1) {
            aiv[u] += __shfl_down_sync(0xffffffffu, aiv[u], off, 16);
            ajv[u] += __shfl_down_sync(0xffffffffu, ajv[u], off, 16);
        }
    }
    if (tx == 0) {
#pragma unroll
        for (int u = 0; u < 8; u++) {
            int gr = row0 + r0 + u;
            if (gr < NN) {
                atomicAdd(&ai[2 * gr + h], aiv[u]);
                atomicAdd(&aj[2 * gr + h], ajv[u]);
            }
        }
    }
}

// ---------------- softmax weights: warp per dst node (register-cached) ------
__global__ void weights_kernel(int layer) {
    int gw = (blockIdx.x * 256 + threadIdx.x) >> 5;
    int lane = threadIdx.x & 31;
    if (gw >= NN) return;
    const int v = gw;
    const float* ai = (layer == 0) ? g_ai : g_ai2;
    const float* aj = (layer == 0) ? g_aj : g_aj2;
    int beg = g_rowptr[v], deg = g_rowptr[v + 1] - beg;
    float ajv0 = aj[2 * v], ajv1 = aj[2 * v + 1];

    int s0 = 0;
    float e0r = -1e30f, e1r = -1e30f;
    if (lane < deg) {
        s0 = __ldg(&g_src[beg + lane]);
        float e0 = ai[2 * s0] + ajv0;     e0r = e0 > 0.f ? e0 : 0.2f * e0;
        float e1 = ai[2 * s0 + 1] + ajv1; e1r = e1 > 0.f ? e1 : 0.2f * e1;
    }
    float m0 = e0r, m1 = e1r;
    for (int i = 32 + lane; i < deg; i += 32) {
        int s = __ldg(&g_src[beg + i]);
        float e0 = ai[2 * s] + ajv0;     e0 = e0 > 0.f ? e0 : 0.2f * e0;
        float e1 = ai[2 * s + 1] + ajv1; e1 = e1 > 0.f ? e1 : 0.2f * e1;
        m0 = fmaxf(m0, e0); m1 = fmaxf(m1, e1);
    }
#pragma unroll
    for (int o = 16; o > 0; o >>= 1) {
        m0 = fmaxf(m0, __shfl_xor_sync(0xffffffff, m0, o));
        m1 = fmaxf(m1, __shfl_xor_sync(0xffffffff, m1, o));
    }

    float d0 = (lane < deg) ? __expf(e0r - m0) : 0.f;
    float d1 = (lane < deg) ? __expf(e1r - m1) : 0.f;
    for (int i = 32 + lane; i < deg; i += 32) {
        int s = __ldg(&g_src[beg + i]);
        float e0 = ai[2 * s] + ajv0;     e0 = e0 > 0.f ? e0 : 0.2f * e0;
        float e1 = ai[2 * s + 1] + ajv1; e1 = e1 > 0.f ? e1 : 0.2f * e1;
        d0 += __expf(e0 - m0); d1 += __expf(e1 - m1);
    }
#pragma unroll
    for (int o = 16; o > 0; o >>= 1) {
        d0 += __shfl_xor_sync(0xffffffff, d0, o);
        d1 += __shfl_xor_sync(0xffffffff, d1, o);
    }
    float inv_d0 = 1.f / (d0 + 1e-16f);
    float inv_d1 = 1.f / (d1 + 1e-16f);

    if (lane < deg) {
        float w0 = __expf(e0r - m0) * inv_d0;
        float w1 = __expf(e1r - m1) * inv_d1;
        g_ew[beg + lane] = make_float4(w0, w1, __int_as_float(s0), 0.f);
    }
    for (int i = 32 + lane; i < deg; i += 32) {
        int s = __ldg(&g_src[beg + i]);
        float e0 = ai[2 * s] + ajv0;     e0 = e0 > 0.f ? e0 : 0.2f * e0;
        float e1 = ai[2 * s + 1] + ajv1; e1 = e1 > 0.f ? e1 : 0.2f * e1;
        float w0 = __expf(e0 - m0) * inv_d0;
        float w1 = __expf(e1 - m1) * inv_d1;
        g_ew[beg + i] = make_float4(w0, w1, __int_as_float(s), 0.f);
    }
}

// ---------------- aggregation: block per dst, 4 edges x 64 half4-lanes ------
// mode 0 (layer 1): post -> g_x1 only.
// mode 1 (layer 2): pre -> g_preh (fp16), post -> ext_post.
__global__ void aggregate_kernel(const float* __restrict__ bias,
                                 float* __restrict__ ext_post, int mode) {
    const int v = blockIdx.x;
    const int t = threadIdx.x;
    const int j = t >> 6;        // edge slot within group of 4
    const int q = t & 63;        // half4 lane (256 halves per row)
    const int head = q >> 5;     // q<32 -> head0, else head1 (warp-uniform)
    __shared__ float4 red[256];

    int beg = g_rowptr[v], deg = g_rowptr[v + 1] - beg;
    const uint2* xph2 = (const uint2*)g_xph;

    float4 acc = make_float4(0.f, 0.f, 0.f, 0.f);
    float4 acc2 = make_float4(0.f, 0.f, 0.f, 0.f);
    int i = j;
    for (; i + 4 < deg; i += 8) {   // two independent chains
        float4 ewa = __ldg(&g_ew[beg + i]);
        float4 ewb = __ldg(&g_ew[beg + i + 4]);
        float wa = head ? ewa.y : ewa.x;
        float wb = head ? ewb.y : ewb.x;
        uint2 ua = xph2[(size_t)__float_as_int(ewa.z) * 64 + q];
        uint2 ub = xph2[(size_t)__float_as_int(ewb.z) * 64 + q];
        float2 a01 = __half22float2(*(__half2*)&ua.x);
        float2 a23 = __half22float2(*(__half2*)&ua.y);
        float2 b01 = __half22float2(*(__half2*)&ub.x);
        float2 b23 = __half22float2(*(__half2*)&ub.y);
        acc.x += wa * a01.x; acc.y += wa * a01.y;
        acc.z += wa * a23.x; acc.w += wa * a23.y;
        acc2.x += wb * b01.x; acc2.y += wb * b01.y;
        acc2.z += wb * b23.x; acc2.w += wb * b23.y;
    }
    for (; i < deg; i += 4) {
        float4 ew = __ldg(&g_ew[beg + i]);
        float w = head ? ew.y : ew.x;
        uint2 u = xph2[(size_t)__float_as_int(ew.z) * 64 + q];
        float2 a01 = __half22float2(*(__half2*)&u.x);
        float2 a23 = __half22float2(*(__half2*)&u.y);
        acc.x += w * a01.x; acc.y += w * a01.y;
        acc.z += w * a23.x; acc.w += w * a23.y;
    }
    acc.x += acc2.x; acc.y += acc2.y; acc.z += acc2.z; acc.w += acc2.w;

    red[t] = acc;
    __syncthreads();
    if (t < 64) {
        float4 a = red[t], b = red[64 + t], c = red[128 + t], d = red[192 + t];
        a.x += b.x + c.x + d.x; a.y += b.y + c.y + d.y;
        a.z += b.z + c.z + d.z; a.w += b.w + c.w + d.w;
        red[t] = a;
    }
    __syncthreads();
    if (t < 32) {
        float4 h0 = red[t], h1 = red[32 + t];
        float4 bb = __ldg(&((const float4*)bias)[t]);
        float4 o;
        o.x = (h0.x + h1.x) * 0.5f + bb.x;
        o.y = (h0.y + h1.y) * 0.5f + bb.y;
        o.z = (h0.z + h1.z) * 0.5f + bb.z;
        o.w = (h0.w + h1.w) * 0.5f + bb.w;
        float4 p;
        p.x = o.x > 0.f ? o.x : 0.01f * o.x;
        p.y = o.y > 0.f ? o.y : 0.01f * o.y;
        p.z = o.z > 0.f ? o.z : 0.01f * o.z;
        p.w = o.w > 0.f ? o.w : 0.01f * o.w;
        if (mode == 0) {
            ((float4*)g_x1)[(size_t)v * 32 + t] = p;
        } else {
            // fp16 pre-activation for the score head (sole consumer)
            __half2 pA = __floats2half2_rn(o.x, o.y);
            __half2 pB = __floats2half2_rn(o.z, o.w);
            uint2 u;
            u.x = *(unsigned int*)&pA;
            u.y = *(unsigned int*)&pB;
            ((uint2*)g_preh)[(size_t)v * 32 + t] = u;
            ((float4*)ext_post)[(size_t)v * 32 + t] = p;
        }
    }
}

// ---------------- edge score head (fp16 gathered rows) ----------------------
__global__ void score_kernel(const int* __restrict__ ei,
                             const float* __restrict__ ea,
                             float* __restrict__ out) {
    int gw = (blockIdx.x * 256 + threadIdx.x) >> 5;
    if (gw >= EE) return;
    int lane = threadIdx.x & 31;
    int s = ei[gw], d = ei[EE + gw];
    const uint2* xs = (const uint2*)g_preh + (size_t)s * 32;
    const uint2* xd = (const uint2*)g_preh + (size_t)d * 32;
    const float4* e4 = (const float4*)(ea + (size_t)gw * 128);
    uint2 us = xs[lane], ud = xd[lane];
    float4 c = e4[lane];
    float2 s01 = __half22float2(*(__half2*)&us.x);
    float2 s23 = __half22float2(*(__half2*)&us.y);
    float2 d01 = __half22float2(*(__half2*)&ud.x);
    float2 d23 = __half22float2(*(__half2*)&ud.y);
    float acc = s01.x * d01.x * c.x + s01.y * d01.y * c.y
              + s23.x * d23.x * c.z + s23.y * d23.y * c.w;
#pragma unroll
    for (int o = 16; o > 0; o >>= 1) acc += __shfl_xor_sync(0xffffffff, acc, o);
    if (lane == 0) out[gw] = 1.f / (1.f + __expf(-acc));
}

// ---------------- launch -----------------------------------------------------
extern "C" void kernel_launch(void* const* d_in, const int* in_sizes, int n_in,
                              void* d_out, int out_size) {
    const float* x   = (const float*)d_in[0];
    const int*   ei  = (const int*)d_in[1];
    const float* ea  = (const float*)d_in[2];
    const float* W1  = (const float*)d_in[3];
    const float* as1 = (const float*)d_in[4];
    const float* ad1 = (const float*)d_in[5];
    const float* b1  = (const float*)d_in[6];
    const float* W2  = (const float*)d_in[7];
    const float* as2 = (const float*)d_in[8];
    const float* ad2 = (const float*)d_in[9];
    const float* b2  = (const float*)d_in[10];

    float* out_x  = (float*)d_out;
    float* out_sc = out_x + (size_t)NN * CC;

    // CSR build (topology shared by both layers) + zero attn — single stream
    init_kernel<<<(NN * HH + 255) / 256, 256>>>();
    count_kernel<<<(EE + 255) / 256, 256>>>(ei);
    scan_pass1<<<NBLK, 256>>>();
    scan_pass2<<<1, 256>>>();
    scan_pass3<<<NBLK, 256>>>();
    scatter_kernel<<<(ETOT + 255) / 256, 256>>>(ei);

    dim3 ggrid((NN + 127) / 128, 4);
    int wblocks = (NN * 32 + 255) / 256;

    // layer 1
    gemm_kernel<<<ggrid, 256>>>(x, 0, W1, as1, ad1);
    weights_kernel<<<wblocks, 256>>>(0);
    aggregate_kernel<<<NN, 256>>>(b1, nullptr, 0);   // -> g_x1

    // layer 2
    gemm_kernel<<<ggrid, 256>>>(nullptr, 1, W2, as2, ad2);
    weights_kernel<<<wblocks, 256>>>(1);
    aggregate_kernel<<<NN, 256>>>(b2, out_x, 1);     // -> g_preh, out_x

    // edge scores from layer-2 pre-activation (fp16 rows, fp32 edge_attr)
    score_kernel<<<(EE * 32 + 255) / 256, 256>>>(ei, ea, out_sc);
}